// round 14
// baseline (speedup 1.0000x reference)
#include <cuda_runtime.h>
#include <cuda_bf16.h>
#include <cstdint>

// out[row, :] = weight[indices[row], :]
// rows = 16384, D = 1024 fp32 = 256 float4/row.
//
// At the HBM write-stream roofline (~3.7TB/s for the mandatory 64MB output
// writes; weight reads ~all L2 hits; 8 structural variants all tie at
// 17.8-19.1us device). Final untried store semantics: st.global.wt
// (write-through) — bypasses the L2 dirty-line/writeback machinery and
// streams directly to DRAM. Tests whether the ceiling is the writeback
// engine (win) or the raw DRAM write bus (tie).
constexpr int ROWS_PER_CTA = 8;

__device__ __forceinline__ float4 ldg_nc(const float4* p) {
    float4 v;
    asm volatile("ld.global.nc.v4.f32 {%0, %1, %2, %3}, [%4];"
                 : "=f"(v.x), "=f"(v.y), "=f"(v.z), "=f"(v.w)
                 : "l"(p));
    return v;
}

__device__ __forceinline__ void stg_wt(float4* p, float4 v) {
    asm volatile("st.global.wt.v4.f32 [%0], {%1, %2, %3, %4};"
                 :: "l"(p), "f"(v.x), "f"(v.y), "f"(v.z), "f"(v.w)
                 : "memory");
}

__global__ void __launch_bounds__(256)
gather_rows_kernel(const int* __restrict__ indices,
                   const float4* __restrict__ weight,
                   float4* __restrict__ out)
{
    __shared__ int sidx[ROWS_PER_CTA];

    const int base_row = blockIdx.x * ROWS_PER_CTA;
    if (threadIdx.x < ROWS_PER_CTA)
        sidx[threadIdx.x] = __ldg(&indices[base_row + threadIdx.x]);
    __syncthreads();

    const int tid = threadIdx.x;

    // 8 ordered, back-to-back LDG.128 (true MLP=8 per thread).
    float4 v[ROWS_PER_CTA];
#pragma unroll
    for (int r = 0; r < ROWS_PER_CTA; r++)
        v[r] = ldg_nc(weight + (size_t)sidx[r] * 256 + tid);

    // Write-through stores: no L2 dirty lines, direct DRAM stream.
    float4* dst = out + (size_t)base_row * 256 + tid;
#pragma unroll
    for (int r = 0; r < ROWS_PER_CTA; r++) {
        stg_wt(dst, v[r]);
        dst += 256;
    }
}

extern "C" void kernel_launch(void* const* d_in, const int* in_sizes, int n_in,
                              void* d_out, int out_size)
{
    // metadata order: indices (int32, 8*2048), weight (float32, 50304*1024)
    const int*    indices = (const int*)d_in[0];
    const float4* weight  = (const float4*)d_in[1];
    float4*       out     = (float4*)d_out;

    const int rows = in_sizes[0];          // 16384
    gather_rows_kernel<<<rows / ROWS_PER_CTA, 256>>>(indices, weight, out);
}

// round 15
// speedup vs baseline: 1.3188x; 1.3188x over previous
#include <cuda_runtime.h>
#include <cuda_bf16.h>
#include <cstdint>

// out[row, :] = weight[indices[row], :]
// rows = 16384, D = 1024 fp32 = 256 float4/row.
//
// FINAL (record: 16.864us e2e, reproduced 4x within ±0.3us noise).
// At the HBM write-stream roofline: the mandatory 64MB output write stream
// drains at ~3.7TB/s regardless of kernel structure. Verified non-binding:
// 9 structural variants (SIMT interleaved, bulk-DMA both directions,
// forced MLP=8, LDG.256, wave geometries) and ALL store semantics
// (.cs, default, evict_last policy, bulk store, .wt — the last proving the
// ceiling is the DRAM write bus, not the writeback engine). Weight reads
// are ~all L2-resident. Config: 8 rows/CTA, 256 threads, ordered MLP=8
// LDG.128 .nc reads, evict-first .cs STG.128 stores, smem-staged indices.
constexpr int ROWS_PER_CTA = 8;

__device__ __forceinline__ float4 ldg_nc(const float4* p) {
    float4 v;
    asm volatile("ld.global.nc.v4.f32 {%0, %1, %2, %3}, [%4];"
                 : "=f"(v.x), "=f"(v.y), "=f"(v.z), "=f"(v.w)
                 : "l"(p));
    return v;
}

__device__ __forceinline__ void stg_cs(float4* p, float4 v) {
    asm volatile("st.global.cs.v4.f32 [%0], {%1, %2, %3, %4};"
                 :: "l"(p), "f"(v.x), "f"(v.y), "f"(v.z), "f"(v.w)
                 : "memory");
}

__global__ void __launch_bounds__(256)
gather_rows_kernel(const int* __restrict__ indices,
                   const float4* __restrict__ weight,
                   float4* __restrict__ out)
{
    __shared__ int sidx[ROWS_PER_CTA];

    const int base_row = blockIdx.x * ROWS_PER_CTA;
    if (threadIdx.x < ROWS_PER_CTA)
        sidx[threadIdx.x] = __ldg(&indices[base_row + threadIdx.x]);
    __syncthreads();

    const int tid = threadIdx.x;

    // 8 ordered, back-to-back LDG.128 (true MLP=8 per thread).
    float4 v[ROWS_PER_CTA];
#pragma unroll
    for (int r = 0; r < ROWS_PER_CTA; r++)
        v[r] = ldg_nc(weight + (size_t)sidx[r] * 256 + tid);

    // Evict-first streaming stores: write-once output, keep L2 for weights.
    float4* dst = out + (size_t)base_row * 256 + tid;
#pragma unroll
    for (int r = 0; r < ROWS_PER_CTA; r++) {
        stg_cs(dst, v[r]);
        dst += 256;
    }
}

extern "C" void kernel_launch(void* const* d_in, const int* in_sizes, int n_in,
                              void* d_out, int out_size)
{
    // metadata order: indices (int32, 8*2048), weight (float32, 50304*1024)
    const int*    indices = (const int*)d_in[0];
    const float4* weight  = (const float4*)d_in[1];
    float4*       out     = (float4*)d_out;

    const int rows = in_sizes[0];          // 16384
    gather_rows_kernel<<<rows / ROWS_PER_CTA, 256>>>(indices, weight, out);
}